// round 16
// baseline (speedup 1.0000x reference)
#include <cuda_runtime.h>
#include <cuda_bf16.h>

#define NTHR 256
#define ST_SIZE 4096   // state (float2), XOR-swizzled power-of-2 layout

// XOR-swizzled state: addr = (i<<9)|(j<<6)|((k&6)<<3) | (c0(i)^c1(j)^c2(k)^c3(l))
__device__ __forceinline__ int hi_c(int m, int x) {
    return m==0 ? (x<<9) : m==1 ? (x<<6) : m==2 ? ((x&6)<<3) : 0;
}
__device__ __forceinline__ int c16_c(int m, int x) {
    return m==0 ? x
         : m==1 ? 9*(x&1)
         : m==2 ? (((x&1)<<3) ^ (x&4) ^ (x&2))
         : (x ^ ((x&4)<<1));
}
__device__ __forceinline__ int addr4i(int i,int j,int k,int l){
    return (i<<9)|(j<<6)|((k&6)<<3)
         | ((c16_c(0,i) ^ c16_c(1,j) ^ c16_c(2,k) ^ c16_c(3,l)) & 15);
}

// Real-matrix gate storage (R14 scheme).
__device__ __align__(16) float  g_bsr[48][432];   // BS real blocks, row pad RK4=(K<=4?4:8)
__device__ __align__(16) float  g_1gr[32][64];    // 8x8 real; 0..15 squeeze, 16..31 disp
__device__ __align__(16) float2 g_wbs[48][64];    // BS input phase w[c*8+d]
__device__ __align__(16) float2 g_w1[32][8];      // 1g input phase

__constant__ int OFFRc[16] = {0,4,12,24,40,80,128,184,248,304,352,392,408,420,428,432};
__constant__ int c_PI[6] = {0,0,0,1,1,2};
__constant__ int c_PJ[6] = {1,2,3,2,3,3};

__device__ __forceinline__ float2 cmul(float2 a, float2 b) {
    return make_float2(fmaf(a.x, b.x, -a.y * b.y), fmaf(a.x, b.y, a.y * b.x));
}
__device__ __forceinline__ void rmac(float2& a, float c, const float2 s) {
    a.x = fmaf(c, s.x, a.x); a.y = fmaf(c, s.y, a.y);
}

// ---------------------------------------------------------------------------
// Scalar phase simulator (R14): pending diagonal phases per mode.
// Gate ids per layer l: BS1 l*20+0..5, squeeze +6..9, BS2 +10..15, disp +16..19.
// ---------------------------------------------------------------------------
__device__ void sim_phases(const float* ph1, const float* ph2, const float* sphi,
                           const float* dr, const float* dphi, const float* kerr,
                           int target, float* ioA, float* ioB)
{
    float pend[4][8];
    for (int m = 0; m < 4; m++) for (int n = 0; n < 8; n++) pend[m][n] = 0.f;
    int id = 0;
    for (int l = 0; l < 4; l++) {
        for (int h = 0; h < 2; h++) {
            const float* P = (h ? ph2 : ph1) + l * 16;
            for (int m = 0; m < 4; m++)
                for (int n = 0; n < 8; n++) pend[m][n] += P[m*4+m] * (float)n;
            for (int p = 0; p < 6; p++) {
                int i = c_PI[p], j = c_PJ[p];
                float ph = P[i*4+j];
                if (id == target) {
                    for (int n = 0; n < 8; n++) {
                        ioA[n] = pend[i][n] + ph * (float)n;
                        ioB[n] = pend[j][n];
                    }
                    return;
                }
                for (int n = 0; n < 8; n++) pend[i][n] = -ph * (float)n;
                for (int n = 0; n < 8; n++) pend[j][n] = P[j*4+i] * (float)n;
                id++;
            }
            if (h == 0) {
                for (int w = 0; w < 4; w++) {
                    float ps = sphi[l*4+w];
                    if (id == target) {
                        for (int n = 0; n < 8; n++) ioA[n] = pend[w][n] - 0.5f*ps*(float)n;
                        return;
                    }
                    for (int n = 0; n < 8; n++) pend[w][n] = 0.5f*ps*(float)n;
                    id++;
                }
            } else {
                for (int w = 0; w < 4; w++) {
                    float th = dr[l*4+w] * sinf(dphi[l*4+w]);
                    if (id == target) {
                        for (int n = 0; n < 8; n++) ioA[n] = pend[w][n] - th*(float)n;
                        return;
                    }
                    for (int n = 0; n < 8; n++) pend[w][n] = th*(float)n;
                    id++;
                }
                for (int w = 0; w < 4; w++)
                    for (int n = 0; n < 8; n++) pend[w][n] += kerr[l*4+w]*(float)(n*n);
            }
        }
    }
}

// ===========================================================================
// Precompute: 80 blocks; real expm matrices + input-phase tables (R14).
// ===========================================================================
__global__ __launch_bounds__(NTHR) void precompute_kernel(
    const float* __restrict__ th1, const float* __restrict__ ph1,
    const float* __restrict__ th2, const float* __restrict__ ph2,
    const float* __restrict__ dr,  const float* __restrict__ dphi,
    const float* __restrict__ sr,  const float* __restrict__ sphi,
    const float* __restrict__ kerr)
{
    __shared__ float2 T[4096 + 128];
    __shared__ float sio[2][8];
    int bid = blockIdx.x, t = threadIdx.x;

    int target;
    if (bid < 48) {
        int l = bid / 12, rem = bid % 12;
        target = l * 20 + (rem / 6) * 10 + (rem % 6);
    } else if (bid < 64) {
        int li = bid - 48; target = (li >> 2) * 20 + 6 + (li & 3);
    } else {
        int li = bid - 64; target = (li >> 2) * 20 + 16 + (li & 3);
    }
    if (t == 0) sim_phases(ph1, ph2, sphi, dr, dphi, kerr, target, sio[0], sio[1]);
    __syncthreads();

    if (bid < 48) {
        int l = bid / 12, rem = bid % 12, intf = rem / 6, p = rem % 6;
        int i = c_PI[p], j = c_PJ[p];
        const float* th = intf ? th2 : th1;
        float theta = th[l*16 + i*4 + j];
        const float scale = 1.0f / 256.0f;

        for (int e = t; e < 4096; e += NTHR) {
            int r = e >> 6, c = e & 63;
            T[e] = make_float2((r == c) ? 1.f : 0.f, 0.f);
        }
        __syncthreads();

        for (int k = 10; k >= 1; k--) {
            float invk = 1.0f / (float)k;
            float2 Cn[16];
            #pragma unroll
            for (int q = 0; q < 16; q++) {
                int e = t * 16 + q;
                int r = e >> 6, c = e & 63;
                int a = r >> 3, b = r & 7;
                float2 acc = make_float2(0.f, 0.f);
                if (a < 7 && b > 0) {
                    float coef = theta * sqrtf((float)((a + 1) * b)) * scale;
                    float2 s = T[((a + 1) * 8 + (b - 1)) * 64 + c];
                    acc.x += coef * s.x; acc.y += coef * s.y;
                }
                if (a > 0 && b < 7) {
                    float coef = -theta * sqrtf((float)(a * (b + 1))) * scale;
                    float2 s = T[((a - 1) * 8 + (b + 1)) * 64 + c];
                    acc.x += coef * s.x; acc.y += coef * s.y;
                }
                acc.x *= invk; acc.y *= invk;
                if (r == c) acc.x += 1.0f;
                Cn[q] = acc;
            }
            __syncthreads();
            #pragma unroll
            for (int q = 0; q < 16; q++) T[t * 16 + q] = Cn[q];
            __syncthreads();
        }
        for (int sq = 0; sq < 8; sq++) {
            float2 Cn[16];
            #pragma unroll
            for (int q = 0; q < 16; q++) {
                int e = t * 16 + q;
                int r = e >> 6, c = e & 63;
                float2 acc = make_float2(0.f, 0.f);
                for (int m = 0; m < 64; m++) {
                    float2 av = T[r * 64 + m];
                    float2 bv = T[m * 64 + c];
                    acc.x = fmaf(av.x, bv.x, acc.x); acc.x = fmaf(-av.y, bv.y, acc.x);
                    acc.y = fmaf(av.x, bv.y, acc.y); acc.y = fmaf(av.y, bv.x, acc.y);
                }
                Cn[q] = acc;
            }
            __syncthreads();
            #pragma unroll
            for (int q = 0; q < 16; q++) T[t * 16 + q] = Cn[q];
            __syncthreads();
        }

        for (int e2 = t; e2 < 432; e2 += NTHR) {
            int n = 0;
            #pragma unroll
            for (int m = 1; m < 15; m++) if (e2 >= OFFRc[m]) n = m;
            int K = 8 - ((n < 7) ? (7 - n) : (n - 7));
            int RK4 = (K <= 4) ? 4 : 8;
            int LO = (n > 7) ? (n - 7) : 0;
            int loc = e2 - OFFRc[n];
            int a = loc / RK4, col = loc % RK4;
            float v = 0.f;
            if (col < K) {
                int A = LO + a, Bq = n - A, C = LO + col, Dq = n - C;
                v = T[(A * 8 + Bq) * 64 + (C * 8 + Dq)].x;
            }
            g_bsr[bid][e2] = v;
        }
        if (t < 64) {
            float ang = sio[0][t >> 3] + sio[1][t & 7];
            float sn, cn; sincosf(ang, &sn, &cn);
            g_wbs[bid][t] = make_float2(cn, sn);
        }
    } else {
        int idx = bid - 48;
        bool is_sq = (idx < 16);
        int li = is_sq ? idx : (idx - 16);
        float2* Tsm = T;
        float2* Hsm = T + 64;
        int r = t >> 3, c = t & 7;

        if (t < 64) {
            float h = 0.f;
            if (is_sq) {
                float rv = sr[li];
                if (c == r + 2) h += 0.5f * rv * sqrtf((float)((r + 1) * (r + 2)));
                if (c + 2 == r) h += -0.5f * rv * sqrtf((float)((c + 1) * (c + 2)));
            } else {
                float mm = dr[li] * cosf(dphi[li]);
                if (c + 1 == r) h += mm * sqrtf((float)r);
                if (c == r + 1) h += -mm * sqrtf((float)(r + 1));
            }
            h *= (1.0f / 16.0f);
            Hsm[t] = make_float2(h, 0.f);
            Tsm[t] = make_float2((r == c) ? 1.f : 0.f, 0.f);
        }
        __syncthreads();

        for (int k = 10; k >= 1; k--) {
            float v = 0.f;
            if (t < 64) {
                #pragma unroll
                for (int m = 0; m < 8; m++)
                    v = fmaf(Hsm[r * 8 + m].x, Tsm[m * 8 + c].x, v);
                v = v / (float)k + ((r == c) ? 1.f : 0.f);
            }
            __syncthreads();
            if (t < 64) Tsm[t] = make_float2(v, 0.f);
            __syncthreads();
        }
        for (int sq = 0; sq < 4; sq++) {
            float v = 0.f;
            if (t < 64) {
                #pragma unroll
                for (int m = 0; m < 8; m++)
                    v = fmaf(Tsm[r * 8 + m].x, Tsm[m * 8 + c].x, v);
            }
            __syncthreads();
            if (t < 64) Tsm[t] = make_float2(v, 0.f);
            __syncthreads();
        }
        if (t < 64) g_1gr[(is_sq ? 0 : 16) + li][t] = Tsm[t].x;
        if (t < 8) {
            float sn, cn; sincosf(sio[0][t], &sn, &cn);
            g_w1[(is_sq ? 0 : 16) + li][t] = make_float2(cn, sn);
        }
    }
}

// ===========================================================================
// Main kernel pieces; in-place state, swizzled layout (R11 maps).
// ===========================================================================

// K x K REAL block GEMV + phase fold, this thread's fiber (SH,SL).
template<int K, int N, int M1, int M2, int F4OFF>
__device__ __forceinline__ void bs_block(const float4* __restrict__ U4,
                                         const float2* __restrict__ W,
                                         int SH, int SL)
{
    extern __shared__ float2 sm[];
    constexpr int LO = (N > 7) ? (N - 7) : 0;
    constexpr int R4 = (K <= 4) ? 1 : 2;
    float2 inv[K];
    #pragma unroll
    for (int c = 0; c < K; c++) {
        int AH = hi_c(M1, LO + c) + hi_c(M2, N - LO - c);
        int AL = c16_c(M1, LO + c) ^ c16_c(M2, N - LO - c);
        float2 w = __ldg(W + (LO + c) * 8 + (N - LO - c));
        inv[c] = cmul(sm[SH + AH + (SL ^ AL)], w);
    }
    #pragma unroll
    for (int a = 0; a < K; a++) {
        float2 acc = make_float2(0.f, 0.f);
        #pragma unroll
        for (int q = 0; q < R4; q++) {
            float4 u = __ldg(U4 + F4OFF + a * R4 + q);
            int e = 4 * q;
            rmac(acc, u.x, inv[e]);
            if (e + 1 < K) rmac(acc, u.y, inv[e + 1]);
            if (e + 2 < K) rmac(acc, u.z, inv[e + 2]);
            if (e + 3 < K) rmac(acc, u.w, inv[e + 3]);
        }
        int AH = hi_c(M1, LO + a) + hi_c(M2, N - LO - a);
        int AL = c16_c(M1, LO + a) ^ c16_c(M2, N - LO - a);
        sm[SH + AH + (SL ^ AL)] = acc;
    }
}

template<int P>
__device__ __noinline__ void bs_gate(const float4* __restrict__ U4,
                                     const float2* __restrict__ W,
                                     int og, int q0, int q1)
{
    constexpr int M1 = (P < 3) ? 0 : (P < 5) ? 1 : 2;
    constexpr int M2 = (P == 0) ? 1 : (P == 1 || P == 3) ? 2 : 3;
    constexpr int MA = (P == 0) ? 2 : (P == 1 || P == 2 || P == 5) ? 1 : 0;
    constexpr int MB = (P == 2 || P == 4) ? 2 : (P == 5) ? 0 : 3;
    int xa = q0;
    if (P == 3) xa = ((q0 & 6) >> 1) | ((q0 & 1) << 2);
    int SH = hi_c(MA, xa) + hi_c(MB, q1);
    int SL = c16_c(MA, xa) ^ c16_c(MB, q1);

    if (og == 0) {
        bs_block<8, 7, M1, M2, 46>(U4, W, SH, SL);
        bs_block<4, 3, M1, M2,  6>(U4, W, SH, SL);
        bs_block<2, 1, M1, M2,  1>(U4, W, SH, SL);
        bs_block<1, 0, M1, M2,  0>(U4, W, SH, SL);
    } else if (og == 1) {
        bs_block<7, 6, M1, M2, 32>(U4, W, SH, SL);
        bs_block<5, 4, M1, M2, 10>(U4, W, SH, SL);
        bs_block<3, 2, M1, M2,  3>(U4, W, SH, SL);
        bs_block<2,13, M1, M2,105>(U4, W, SH, SL);
    } else if (og == 2) {
        bs_block<7, 8, M1, M2, 62>(U4, W, SH, SL);
        bs_block<5,10, M1, M2, 88>(U4, W, SH, SL);
        bs_block<3,12, M1, M2,102>(U4, W, SH, SL);
        bs_block<1,14, M1, M2,107>(U4, W, SH, SL);
    } else {
        bs_block<6, 5, M1, M2, 20>(U4, W, SH, SL);
        bs_block<6, 9, M1, M2, 76>(U4, W, SH, SL);
        bs_block<4,11, M1, M2, 98>(U4, W, SH, SL);
    }
}

// Single-mode 8x8 REAL gate + input phase; in place; 2 fibers/thread.
template<int MODE>
__device__ __noinline__ void apply1g_t(const float4* __restrict__ U4,
                                       const float2* __restrict__ W, int t)
{
    extern __shared__ float2 sm[];
    int SH1, SL1, SH2, SL2;
    if (MODE == 0) {
        int l_ = t & 7, k_ = (t >> 3) & 7, j_ = (t >> 6) & 3;
        SH1 = hi_c(1,j_)   + hi_c(2,k_) + hi_c(3,l_);
        SL1 = c16_c(1,j_)   ^ c16_c(2,k_) ^ c16_c(3,l_);
        SH2 = hi_c(1,j_+4) + hi_c(2,k_) + hi_c(3,l_);
        SL2 = c16_c(1,j_+4) ^ c16_c(2,k_) ^ c16_c(3,l_);
    } else if (MODE == 1) {
        int l_ = t & 7, i_ = (((t >> 3) & 1) << 2) | ((t >> 4) & 3), k_ = (t >> 6) & 3;
        SH1 = hi_c(0,i_) + hi_c(2,k_)   + hi_c(3,l_);
        SL1 = c16_c(0,i_) ^ c16_c(2,k_)   ^ c16_c(3,l_);
        SH2 = hi_c(0,i_) + hi_c(2,k_+4) + hi_c(3,l_);
        SL2 = c16_c(0,i_) ^ c16_c(2,k_+4) ^ c16_c(3,l_);
    } else if (MODE == 2) {
        int l_ = t & 7, j_ = ((t >> 3) & 1) | (((t >> 4) & 3) << 1), i_ = (t >> 6) & 3;
        SH1 = hi_c(0,i_)   + hi_c(1,j_) + hi_c(3,l_);
        SL1 = c16_c(0,i_)   ^ c16_c(1,j_) ^ c16_c(3,l_);
        SH2 = hi_c(0,i_+4) + hi_c(1,j_) + hi_c(3,l_);
        SL2 = c16_c(0,i_+4) ^ c16_c(1,j_) ^ c16_c(3,l_);
    } else {
        int i_ = t & 7, j_ = ((t >> 3) & 1) | (((t >> 4) & 3) << 1), k_ = (t >> 6) & 3;
        SH1 = hi_c(0,i_) + hi_c(1,j_) + hi_c(2,k_);
        SL1 = c16_c(0,i_) ^ c16_c(1,j_) ^ c16_c(2,k_);
        SH2 = hi_c(0,i_) + hi_c(1,j_) + hi_c(2,k_+4);
        SL2 = c16_c(0,i_) ^ c16_c(1,j_) ^ c16_c(2,k_+4);
    }

    float2 sva[8], svb[8];
    #pragma unroll
    for (int c = 0; c < 8; c++) {
        int AH = hi_c(MODE, c), AL = c16_c(MODE, c);
        float2 w = __ldg(W + c);
        sva[c] = cmul(sm[SH1 + AH + (SL1 ^ AL)], w);
        svb[c] = cmul(sm[SH2 + AH + (SL2 ^ AL)], w);
    }
    #pragma unroll
    for (int o = 0; o < 8; o++) {
        float4 u0 = __ldg(U4 + o * 2), u1 = __ldg(U4 + o * 2 + 1);
        float2 aa = make_float2(0.f, 0.f), ab = make_float2(0.f, 0.f);
        rmac(aa, u0.x, sva[0]); rmac(aa, u0.y, sva[1]);
        rmac(aa, u0.z, sva[2]); rmac(aa, u0.w, sva[3]);
        rmac(aa, u1.x, sva[4]); rmac(aa, u1.y, sva[5]);
        rmac(aa, u1.z, sva[6]); rmac(aa, u1.w, sva[7]);
        rmac(ab, u0.x, svb[0]); rmac(ab, u0.y, svb[1]);
        rmac(ab, u0.z, svb[2]); rmac(ab, u0.w, svb[3]);
        rmac(ab, u1.x, svb[4]); rmac(ab, u1.y, svb[5]);
        rmac(ab, u1.z, svb[6]); rmac(ab, u1.w, svb[7]);
        int AH = hi_c(MODE, o), AL = c16_c(MODE, o);
        sm[SH1 + AH + (SL1 ^ AL)] = aa;
        sm[SH2 + AH + (SL2 ^ AL)] = ab;
    }
}

// ===========================================================================
// Main kernel: one CTA per batch element, in-place state, 1 barrier/gate.
// ===========================================================================
__global__ __launch_bounds__(NTHR, 3) void qnn_main(
    const float* __restrict__ x, float* __restrict__ out)
{
    extern __shared__ float2 sm[];
    float* enc = (float*)(sm + ST_SIZE);   // encH[256] encA[256] encB[256] red[32]
    float* encH = enc, *encA = enc + 256, *encB = enc + 512;
    float* red = enc + 768;

    int b = blockIdx.x, t = threadIdx.x;
    int wid = t >> 5, lane = t & 31;

    // ---- per-sample encoding expm: E_g = expm(x_g (AD - A)), real 8x8 ----
    {
        int g = t >> 6, e = t & 63, r = e >> 3, c = e & 7;
        float xv = __ldg(&x[b * 4 + g]);
        float sc = xv * (1.0f / 64.0f);   // 6 squarings
        float h = 0.f;
        if (c == r - 1) h = sc * sqrtf((float)r);
        else if (c == r + 1) h = -sc * sqrtf((float)(r + 1));
        encH[g * 64 + e] = h;
        encA[g * 64 + e] = (r == c) ? 1.f : 0.f;
        __syncthreads();

        float* Ta = encA + g * 64;
        float* Tb = encB + g * 64;
        for (int k = 9; k >= 1; k--) {
            float acc = 0.f;
            #pragma unroll
            for (int m = 0; m < 8; m++)
                acc = fmaf(encH[g * 64 + r * 8 + m], Ta[m * 8 + c], acc);
            float v = acc / (float)k + ((r == c) ? 1.f : 0.f);
            Tb[e] = v;
            __syncthreads();
            float* tmp = Ta; Ta = Tb; Tb = tmp;
        }
        for (int sq = 0; sq < 6; sq++) {
            float acc = 0.f;
            #pragma unroll
            for (int m = 0; m < 8; m++) acc = fmaf(Ta[r * 8 + m], Ta[m * 8 + c], acc);
            Tb[e] = acc;
            __syncthreads();
            float* tmp = Ta; Ta = Tb; Tb = tmp;
        }
        // final matrix lives in encB region (15 swaps)
    }

    // ---- init state: outer product of E_g column 0 ----
    {
        int i_ = t & 7, j_ = ((t >> 3) & 1) | (((t >> 4) & 3) << 1), k_ = (t >> 6) & 3;
        float e0 = encB[0 * 64 + i_ * 8];
        float e1 = encB[1 * 64 + j_ * 8];
        #pragma unroll
        for (int kk = 0; kk < 2; kk++) {
            int k2 = k_ + 4 * kk;
            float e01 = e0 * e1 * encB[2 * 64 + k2 * 8];
            #pragma unroll
            for (int l2 = 0; l2 < 8; l2++)
                sm[addr4i(i_, j_, k2, l2)] =
                    make_float2(e01 * encB[3 * 64 + l2 * 8], 0.f);
        }
    }
    __syncthreads();

    // ---- circuit ----
    int f = t & 63, og = t >> 6;
    int q0 = f >> 3, q1 = f & 7;

    #pragma unroll 1
    for (int l = 0; l < 4; l++) {
        #pragma unroll 1
        for (int hh = 0; hh < 2; hh++) {
            int gb = l * 12 + hh * 6;
            bs_gate<0>((const float4*)g_bsr[gb+0], g_wbs[gb+0], og, q0, q1); __syncthreads();
            bs_gate<1>((const float4*)g_bsr[gb+1], g_wbs[gb+1], og, q0, q1); __syncthreads();
            bs_gate<2>((const float4*)g_bsr[gb+2], g_wbs[gb+2], og, q0, q1); __syncthreads();
            bs_gate<3>((const float4*)g_bsr[gb+3], g_wbs[gb+3], og, q0, q1); __syncthreads();
            bs_gate<4>((const float4*)g_bsr[gb+4], g_wbs[gb+4], og, q0, q1); __syncthreads();
            bs_gate<5>((const float4*)g_bsr[gb+5], g_wbs[gb+5], og, q0, q1); __syncthreads();
            int g1 = (hh ? 16 : 0) + l * 4;
            apply1g_t<0>((const float4*)g_1gr[g1+0], g_w1[g1+0], t); __syncthreads();
            apply1g_t<1>((const float4*)g_1gr[g1+1], g_w1[g1+1], t); __syncthreads();
            apply1g_t<2>((const float4*)g_1gr[g1+2], g_w1[g1+2], t); __syncthreads();
            apply1g_t<3>((const float4*)g_1gr[g1+3], g_w1[g1+3], t); __syncthreads();
        }
    }

    // ---- expectations <n_w> (residual diagonal phases drop out of |psi|^2) ----
    float ev0 = 0.f, ev1 = 0.f, ev2 = 0.f, ev3 = 0.f;
    {
        int i_ = t & 7, j_ = ((t >> 3) & 1) | (((t >> 4) & 3) << 1), k_ = (t >> 6) & 3;
        #pragma unroll
        for (int kk = 0; kk < 2; kk++) {
            int k2 = k_ + 4 * kk;
            #pragma unroll
            for (int l2 = 0; l2 < 8; l2++) {
                float2 a = sm[addr4i(i_, j_, k2, l2)];
                float p = a.x * a.x + a.y * a.y;
                ev0 = fmaf(p, (float)i_, ev0);
                ev1 = fmaf(p, (float)j_, ev1);
                ev2 = fmaf(p, (float)k2, ev2);
                ev3 = fmaf(p, (float)l2, ev3);
            }
        }
    }
    #pragma unroll
    for (int off2 = 16; off2; off2 >>= 1) {
        ev0 += __shfl_down_sync(0xFFFFFFFFu, ev0, off2);
        ev1 += __shfl_down_sync(0xFFFFFFFFu, ev1, off2);
        ev2 += __shfl_down_sync(0xFFFFFFFFu, ev2, off2);
        ev3 += __shfl_down_sync(0xFFFFFFFFu, ev3, off2);
    }
    if (lane == 0) {
        red[0 * 8 + wid] = ev0; red[1 * 8 + wid] = ev1;
        red[2 * 8 + wid] = ev2; red[3 * 8 + wid] = ev3;
    }
    __syncthreads();
    if (t < 4) {
        float s = 0.f;
        #pragma unroll
        for (int wv = 0; wv < 8; wv++) s += red[t * 8 + wv];
        out[b * 4 + t] = s;
    }
}

extern "C" void kernel_launch(void* const* d_in, const int* in_sizes, int n_in,
                              void* d_out, int out_size) {
    const float* x    = (const float*)d_in[0];
    const float* th1  = (const float*)d_in[1];
    const float* ph1  = (const float*)d_in[2];
    const float* th2  = (const float*)d_in[3];
    const float* ph2  = (const float*)d_in[4];
    const float* dr   = (const float*)d_in[5];
    const float* dphi = (const float*)d_in[6];
    const float* sr   = (const float*)d_in[7];
    const float* sphi = (const float*)d_in[8];
    const float* kerr = (const float*)d_in[9];
    float* out = (float*)d_out;
    int Bn = in_sizes[0] / 4;

    int smem_bytes = ST_SIZE * (int)sizeof(float2) + (768 + 32) * (int)sizeof(float);
    cudaFuncSetAttribute(qnn_main, cudaFuncAttributeMaxDynamicSharedMemorySize, smem_bytes);

    precompute_kernel<<<80, NTHR>>>(th1, ph1, th2, ph2, dr, dphi, sr, sphi, kerr);
    qnn_main<<<Bn, NTHR, smem_bytes>>>(x, out);
}